// round 15
// baseline (speedup 1.0000x reference)
#include <cuda_runtime.h>
#include <cuda_bf16.h>

// AdditiveDTMGP: 3-stage additive deep GP, Laplace kernel on dyadic design
// u_i = i/64 (i=1..63), whitened by Rinv (upper-triangular), reparam weights.
//
// Exact split: exp(-|x-u|) = e^{-x}e^{u} (u<=x) / e^{x}e^{-u} (u>x) collapses
// each 63-term sum to a 2-term table lookup at j = floor(64x). Stage 1 tables
// premultiplied by e^{-+j/64}, stored (P,Q) fp32. Stages 2/3 exact (A,B)+exp.
//
// SINGLE FUSED KERNEL, attempt 3. R13/R14 failure root cause: build Phase B
// read Rinv rows directly from global with a different row per lane ->
// ~32 L1 wavefronts per LDG -> ~16k wavefronts/block of replay serialization.
// Fix: stage Rinv into SMEM with coalesced float4 loads (R12-proven path;
// LDS reads are bank-conflict-free: word-stride 63 => bank-stride 31).
// Static SMEM 19.6KB * 8 blocks = 160KB <= 227KB, so (256,8) residency and
// the single-wave no-deadlock guarantee hold (grid <= 1184).

#define MM 63
#define NBLK 209          // 128 stage1 + 64 stage2 + 16 stage3 + 1 bias
#define MAXGRID 1184      // 148 SMs * 8 blocks guaranteed resident

__device__ float2 g_T1[32 * 64 * 16];   // stage1 [f][j][o] : (P, Q)
__device__ float2 g_T2[16 * 64 * 16];   // stage2 [f][j][o] : (A, B)
__device__ float2 g_T3[64 * 16];        // stage3 [j][f]    : (A, B)
__device__ float  g_bsum1[16];
__device__ float  g_bsum2[16];
__device__ float  g_bsum3;
__device__ float  g_klpart[NBLK];
__device__ int    g_ready;              // zero-init; reset at end of launch
__device__ int    g_done;

__device__ __forceinline__ float kl_term(float mu, float s) {
    return fmaf(0.5f, fmaf(s, s, mu * mu), -__logf(s)) - 0.5f;
}

// Embed 6-bit j into low mantissa bits of v (rounded): <= ~63-ulp perturbation.
__device__ __forceinline__ float embed_j(float v, int j) {
    unsigned b = (__float_as_uint(v) + 32u) & ~63u;
    return __uint_as_float(b | (unsigned)j);
}

__global__ void __launch_bounds__(256, 8) fused_kernel(
    const float* __restrict__ x,
    const float* __restrict__ U, const float* __restrict__ Rinv,
    const float* __restrict__ mw1, const float* __restrict__ rw1, const float* __restrict__ ew1,
    const float* __restrict__ mw2, const float* __restrict__ rw2, const float* __restrict__ ew2,
    const float* __restrict__ mw3, const float* __restrict__ rw3, const float* __restrict__ ew3,
    const float* __restrict__ mb1, const float* __restrict__ rb1, const float* __restrict__ eb1,
    const float* __restrict__ mb2, const float* __restrict__ rb2, const float* __restrict__ eb2,
    const float* __restrict__ mb3, const float* __restrict__ rb3, const float* __restrict__ eb3,
    float* __restrict__ out, int nB, int numTiles, int klIdx)
{
    // sbuf: build scratch (sW/sP/sQ/red/wt), later aliased as fwd tw slots.
    // sR: Rinv staging, build phase only.
    __shared__ __align__(16) float sbuf[1040];
    __shared__ __align__(16) float sR[3972];
    const int t = threadIdx.x;
    const int blk = blockIdx.x;

    // ================= build phase (blocks 0..208) =================
    if (blk < 208) {
        float* sW  = sbuf;          // 4*63 = 252
        float* sP  = sbuf + 256;    // 4*64
        float* sQ  = sbuf + 512;    // 4*64
        float* red = sbuf + 768;    // 256
        float* wtP = sbuf + 1024;   // 8
        float* wtQ = sbuf + 1032;   // 8

        int stage, f, oB, Ocnt, Otot;
        const float *mw, *rw, *ew;
        if (blk < 128) {
            stage = 1; f = blk >> 2; oB = (blk & 3) * 4; Ocnt = 4; Otot = 16;
            mw = mw1; rw = rw1; ew = ew1;
        } else if (blk < 192) {
            int bb = blk - 128;
            stage = 2; f = bb >> 2; oB = (bb & 3) * 4; Ocnt = 4; Otot = 16;
            mw = mw2; rw = rw2; ew = ew2;
        } else {
            stage = 3; f = blk - 192; oB = 0; Ocnt = 1; Otot = 1;
            mw = mw3; rw = rw3; ew = ew3;
        }

        // Coalesced Rinv staging (3969 = 992*4 + 1).
        {
            const float4* R4 = (const float4*)Rinv;
            float4* S4 = (float4*)sR;
            #pragma unroll 4
            for (int i = t; i < 992; i += 256) S4[i] = R4[i];
            if (t == 0) sR[3968] = Rinv[3968];
        }
        sP[t] = 0.f; sQ[t] = 0.f;

        // Phase A: effective weights + weight-KL partial.
        float kl = 0.f;
        #pragma unroll 1
        for (int i = t; i < Ocnt * MM; i += 256) {
            int ol = i / MM, n = i % MM;
            int gi = (f * Otot + oB + ol) * MM + n;
            float mu = mw[gi];
            float s  = log1pf(__expf(rw[gi]));
            sW[i] = mu + s * ew[gi];
            kl += kl_term(mu, s);
        }
        red[t] = kl;
        __syncthreads();

        // Phase B: one V entry per thread, all-SMEM operands (R12-proven).
        #pragma unroll 1
        for (int i = t; i < Ocnt * MM; i += 256) {
            int ol = i / MM, m = i % MM;
            const float* r = &sR[m * MM];
            const float* w = &sW[ol * MM];
            float v = 0.f;
            #pragma unroll
            for (int n = 0; n < MM; n++) v = fmaf(r[n], w[n], v);
            float u = __ldg(&U[m]);
            sP[ol * 64 + (m + 1)] = v * __expf(u);
            sQ[ol * 64 + (m + 1)] = v * __expf(-u);
        }
        __syncthreads();

        // Phase C: segmented scan (segments of 64 = 2 warps).
        {
            const int lane = t & 31, wid = t >> 5;
            float p = sP[t], q = sQ[t];
            #pragma unroll
            for (int d = 1; d < 32; d <<= 1) {
                float np = __shfl_up_sync(0xFFFFFFFFu, p, d);
                float nq = __shfl_up_sync(0xFFFFFFFFu, q, d);
                if (lane >= d) { p += np; q += nq; }
            }
            if (lane == 31) { wtP[wid] = p; wtQ[wid] = q; }
            __syncthreads();
            if (wid & 1) { p += wtP[wid - 1]; q += wtQ[wid - 1]; }
            int seg = t >> 6;
            float qtot = wtQ[seg * 2] + wtQ[seg * 2 + 1];
            float A = p, B = qtot - q;

            if (t < Ocnt * 64) {
                int ol = seg, j = t & 63;
                if (stage == 1) {
                    float jf = (float)j * 0.015625f;
                    float At = A * __expf(-jf);
                    float Bt = B * __expf(jf);
                    g_T1[(f * 64 + j) * 16 + (oB + ol)] = make_float2(At + Bt, Bt - At);
                } else if (stage == 2) {
                    g_T2[(f * 64 + j) * 16 + (oB + ol)] = make_float2(A, B);
                } else {
                    g_T3[j * 16 + f] = make_float2(A, B);
                }
            }
        }
        __syncthreads();

        for (int s = 128; s > 0; s >>= 1) {
            if (t < s) red[t] += red[t + s];
            __syncthreads();
        }
        if (t == 0) {
            g_klpart[blk] = red[0];
            __threadfence();
            atomicAdd(&g_ready, 1);
        }
    } else if (blk == 208) {
        float* red = sbuf + 768;
        float kl = 0.f;
        #pragma unroll 1
        for (int i = t; i < 32 * 16; i += 256) kl += kl_term(mb1[i], log1pf(__expf(rb1[i])));
        #pragma unroll 1
        for (int i = t; i < 16 * 16; i += 256) kl += kl_term(mb2[i], log1pf(__expf(rb2[i])));
        #pragma unroll 1
        for (int i = t; i < 16;      i += 256) kl += kl_term(mb3[i], log1pf(__expf(rb3[i])));
        if (t < 16) {
            float s = 0.f;
            #pragma unroll 1
            for (int f = 0; f < 32; f++) {
                int i = f * 16 + t;
                s += mb1[i] + log1pf(__expf(rb1[i])) * eb1[i];
            }
            g_bsum1[t] = s;
        } else if (t < 32) {
            int o = t - 16;
            float s = 0.f;
            #pragma unroll 1
            for (int f = 0; f < 16; f++) {
                int i = f * 16 + o;
                s += mb2[i] + log1pf(__expf(rb2[i])) * eb2[i];
            }
            g_bsum2[o] = s;
        } else if (t == 32) {
            float s = 0.f;
            #pragma unroll 1
            for (int f = 0; f < 16; f++)
                s += mb3[f] + log1pf(__expf(rb3[f])) * eb3[f];
            g_bsum3 = s;
        }
        red[t] = kl;
        __syncthreads();
        for (int s = 128; s > 0; s >>= 1) {
            if (t < s) red[t] += red[t + s];
            __syncthreads();
        }
        if (t == 0) {
            g_klpart[208] = red[0];
            __threadfence();
            atomicAdd(&g_ready, 1);
        }
    }
    __syncthreads();   // build reads of sbuf done before fwd aliasing writes

    // ================= fwd phase (all blocks) =================
    const int warp = t >> 5, lane = t & 31;
    const int sub = lane >> 4, o = lane & 15;
    const unsigned mask = 0xFFFFu << (sub << 4);
    float2* tw = ((float2*)sbuf) + warp * 64 + sub * 32;

    bool waited = false;
    float bs1 = 0.f, bs2 = 0.f, bs3 = 0.f;

    #pragma unroll 1
    for (int tile = blk; tile < numTiles; tile += gridDim.x) {
        const int b = tile * 16 + warp * 2 + sub;
        const int bc = (b < nB) ? b : (nB - 1);

        // pre-wait: x loads + stage-1 precompute (independent of tables)
        const float xv0 = __ldg(&x[bc * 32 + o]);
        const float xv1 = __ldg(&x[bc * 32 + 16 + o]);
        {
            float j0f = fminf(fmaxf(xv0 * 64.f, 0.f), 63.f);
            int   j0  = (int)j0f;
            float t0  = fmaf((float)j0, -0.015625f, xv0);
            float t02 = t0 * t0;
            tw[o] = make_float2(embed_j(fmaf(t02, 0.5f, 1.f), j0),
                                t0 * fmaf(t02, 0.16666667f, 1.f));
            float j1f = fminf(fmaxf(xv1 * 64.f, 0.f), 63.f);
            int   j1  = (int)j1f;
            float t1  = fmaf((float)j1, -0.015625f, xv1);
            float t12 = t1 * t1;
            tw[16 + o] = make_float2(embed_j(fmaf(t12, 0.5f, 1.f), j1),
                                     t1 * fmaf(t12, 0.16666667f, 1.f));
        }
        __syncwarp();

        if (!waited) {
            if (t == 0) {
                volatile int* vr = &g_ready;
                while (*vr < NBLK) __nanosleep(64);
            }
            __syncthreads();
            __threadfence();   // order table reads after observed flag
            waited = true;

            if (blk == 0 && t < 32) {  // KL output
                float s = 0.f;
                #pragma unroll 1
                for (int i = t; i < NBLK; i += 32) s += g_klpart[i];
                #pragma unroll
                for (int d = 16; d > 0; d >>= 1)
                    s += __shfl_xor_sync(0xFFFFFFFFu, s, d);
                if (t == 0) out[klIdx] = s;
            }
            bs1 = __ldg(&g_bsum1[o]);
            bs2 = __ldg(&g_bsum2[o]);
            bs3 = __ldg(&g_bsum3);
        }

        // ---- stage 1 gathers ----
        const char* base1 = (const char*)g_T1 + o * 8;
        float acc = 0.f;
        #pragma unroll
        for (int f = 0; f < 32; f++) {
            float2 tr = tw[f];
            unsigned jb = (__float_as_uint(tr.x) & 63u) << 7;   // j*128
            const float2 pq = *(const float2*)(base1 + f * 8192 + jb);
            acc = fmaf(pq.x, tr.x, fmaf(pq.y, tr.y, acc));
        }
        float h1 = acc + bs1;
        __syncwarp();

        // ---- stage 2 precompute + gathers ----
        {
            float ex  = __expf(h1);
            float emx = __expf(-h1);
            int j = (int)fminf(fmaxf(h1 * 64.f, 0.f), 63.f);
            tw[o] = make_float2(embed_j(emx, j), ex);
        }
        __syncwarp();

        const char* base2 = (const char*)g_T2 + o * 8;
        acc = 0.f;
        #pragma unroll
        for (int f = 0; f < 16; f++) {
            float2 tr = tw[f];
            unsigned jb = (__float_as_uint(tr.x) & 63u) << 7;
            const float2 ab = *(const float2*)(base2 + f * 8192 + jb);
            acc = fmaf(tr.x, ab.x, fmaf(tr.y, ab.y, acc));
        }
        float h2 = acc + bs2;

        // ---- stage 3: 16 -> 1 ----
        {
            float ex  = __expf(h2);
            float emx = __expf(-h2);
            int j = (int)fminf(fmaxf(h2 * 64.f, 0.f), 63.f);
            float2 tv = __ldg(&g_T3[j * 16 + o]);
            float c = fmaf(emx, tv.x, ex * tv.y);
            c += __shfl_xor_sync(mask, c, 8);
            c += __shfl_xor_sync(mask, c, 4);
            c += __shfl_xor_sync(mask, c, 2);
            c += __shfl_xor_sync(mask, c, 1);
            if (o == 0 && b < nB) out[b] = c + bs3;
        }
        __syncwarp();   // tw reuse safety for next tile
    }

    // ================= self-reset for next launch / graph replay =========
    __syncthreads();
    if (t == 0) {
        int old = atomicAdd(&g_done, 1);
        if (old == (int)gridDim.x - 1) {
            g_ready = 0;
            g_done = 0;
            __threadfence();
        }
    }
}

// ---------------------------------------------------------------------------
extern "C" void kernel_launch(void* const* d_in, const int* in_sizes, int n_in,
                              void* d_out, int out_size)
{
    const float* x    = (const float*)d_in[0];
    const float* U    = (const float*)d_in[1];
    const float* Rinv = (const float*)d_in[2];

    const float* mw1 = (const float*)d_in[3];
    const float* rw1 = (const float*)d_in[4];
    const float* mb1 = (const float*)d_in[5];
    const float* rb1 = (const float*)d_in[6];
    const float* ew1 = (const float*)d_in[7];
    const float* eb1 = (const float*)d_in[8];

    const float* mw2 = (const float*)d_in[9];
    const float* rw2 = (const float*)d_in[10];
    const float* mb2 = (const float*)d_in[11];
    const float* rb2 = (const float*)d_in[12];
    const float* ew2 = (const float*)d_in[13];
    const float* eb2 = (const float*)d_in[14];

    const float* mw3 = (const float*)d_in[15];
    const float* rw3 = (const float*)d_in[16];
    const float* mb3 = (const float*)d_in[17];
    const float* rb3 = (const float*)d_in[18];
    const float* ew3 = (const float*)d_in[19];
    const float* eb3 = (const float*)d_in[20];

    const int nB = in_sizes[0] / 32;
    const int numTiles = (nB + 15) / 16;
    int grid = numTiles;
    if (grid < NBLK)    grid = NBLK;      // build needs 209 blocks
    if (grid > MAXGRID) grid = MAXGRID;   // single-wave residency guarantee
    float* out = (float*)d_out;

    fused_kernel<<<grid, 256>>>(x, U, Rinv,
                                mw1, rw1, ew1, mw2, rw2, ew2, mw3, rw3, ew3,
                                mb1, rb1, eb1, mb2, rb2, eb2, mb3, rb3, eb3,
                                out, nB, numTiles, out_size - 1);
}

// round 16
// speedup vs baseline: 1.5355x; 1.5355x over previous
#include <cuda_runtime.h>
#include <cuda_bf16.h>

// AdditiveDTMGP: 3-stage additive deep GP, Laplace kernel on dyadic design
// u_i = i/64 (i=1..63), whitened by Rinv (upper-triangular), reparam weights.
//
// Exact split: exp(-|x-u|) = e^{-x}e^{u} (u<=x) / e^{x}e^{-u} (u>x) collapses
// each 63-term sum to a 2-term table lookup at j = floor(64x). Stage 1 tables
// premultiplied by e^{-+j/64}, stored (P,Q) fp32. Stages 2/3 exact (A,B)+exp.
//
// R12 architecture (best known: 18.46us): separate build (209 blocks, scan-
// based) + fwd under PDL. Fusion attempts R13-R15 all regressed (build
// time-sliced against parked spinner blocks) and are abandoned.
// This round: fwd gather loops use dual accumulators (even/odd f) — +1 reg,
// splits the FMA chain for load/FMA overlap. Everything else R12-identical.

#define MM 63
#define NBLK 209   // 128 stage1 + 64 stage2 + 16 stage3 + 1 bias

__device__ float2 g_T1[32 * 64 * 16];   // stage1 [f][j][o] : (P, Q)
__device__ float2 g_T2[16 * 64 * 16];   // stage2 [f][j][o] : (A, B)
__device__ float2 g_T3[64 * 16];        // stage3 [j][f]    : (A, B)
__device__ float  g_bsum1[16];
__device__ float  g_bsum2[16];
__device__ float  g_bsum3;
__device__ float  g_klpart[NBLK];

__device__ __forceinline__ float kl_term(float mu, float s) {
    return fmaf(0.5f, fmaf(s, s, mu * mu), -__logf(s)) - 0.5f;
}

// Embed 6-bit j into low mantissa bits of v (rounded): <= ~63-ulp perturbation.
__device__ __forceinline__ float embed_j(float v, int j) {
    unsigned b = (__float_as_uint(v) + 32u) & ~63u;
    return __uint_as_float(b | (unsigned)j);
}

// ---------------------------------------------------------------------------
// Prep: 209 blocks.
//   [0,128)   stage1: f = blk>>2, o-range [(blk&3)*4, +4)
//   [128,192) stage2: f = (blk-128)>>2, o-range [(blk&3)*4, +4)
//   [192,208) stage3: f = blk-192, O=1
//   208       bias sums + bias-KL
// ---------------------------------------------------------------------------
__global__ void __launch_bounds__(256) build_tables(
    const float* __restrict__ U, const float* __restrict__ Rinv,
    const float* __restrict__ mw1, const float* __restrict__ rw1, const float* __restrict__ ew1,
    const float* __restrict__ mw2, const float* __restrict__ rw2, const float* __restrict__ ew2,
    const float* __restrict__ mw3, const float* __restrict__ rw3, const float* __restrict__ ew3,
    const float* __restrict__ mb1, const float* __restrict__ rb1, const float* __restrict__ eb1,
    const float* __restrict__ mb2, const float* __restrict__ rb2, const float* __restrict__ eb2,
    const float* __restrict__ mb3, const float* __restrict__ rb3, const float* __restrict__ eb3)
{
    const int blk = blockIdx.x, t = threadIdx.x;
    __shared__ float red[256];

    if (blk == 208) {
        float kl = 0.f;
        for (int i = t; i < 32 * 16; i += 256) kl += kl_term(mb1[i], log1pf(__expf(rb1[i])));
        for (int i = t; i < 16 * 16; i += 256) kl += kl_term(mb2[i], log1pf(__expf(rb2[i])));
        for (int i = t; i < 16;      i += 256) kl += kl_term(mb3[i], log1pf(__expf(rb3[i])));
        if (t < 16) {
            float s = 0.f;
            for (int f = 0; f < 32; f++) {
                int i = f * 16 + t;
                s += mb1[i] + log1pf(__expf(rb1[i])) * eb1[i];
            }
            g_bsum1[t] = s;
        } else if (t < 32) {
            int o = t - 16;
            float s = 0.f;
            for (int f = 0; f < 16; f++) {
                int i = f * 16 + o;
                s += mb2[i] + log1pf(__expf(rb2[i])) * eb2[i];
            }
            g_bsum2[o] = s;
        } else if (t == 32) {
            float s = 0.f;
            for (int f = 0; f < 16; f++)
                s += mb3[f] + log1pf(__expf(rb3[f])) * eb3[f];
            g_bsum3 = s;
        }
        red[t] = kl;
        __syncthreads();
        for (int s = 128; s > 0; s >>= 1) {
            if (t < s) red[t] += red[t + s];
            __syncthreads();
        }
        if (t == 0) g_klpart[208] = red[0];
        cudaTriggerProgrammaticLaunchCompletion();
        return;
    }

    __shared__ float sR[MM * MM + 1];
    __shared__ float sW[4 * MM];
    __shared__ float sP[4 * 64];   // P[ol][i] = e^{i/64} V[ol][i-1], i=1..63
    __shared__ float sQ[4 * 64];
    __shared__ float sEU[MM], sEMU[MM];
    __shared__ float sEJ[64], sEMJ[64];
    __shared__ float wtP[8], wtQ[8];

    int stage, f, oB, Ocnt, Otot;
    const float *mw, *rw, *ew;
    if (blk < 128) {
        stage = 1; f = blk >> 2; oB = (blk & 3) * 4; Ocnt = 4; Otot = 16;
        mw = mw1; rw = rw1; ew = ew1;
    } else if (blk < 192) {
        int bb = blk - 128;
        stage = 2; f = bb >> 2; oB = (bb & 3) * 4; Ocnt = 4; Otot = 16;
        mw = mw2; rw = rw2; ew = ew2;
    } else {
        stage = 3; f = blk - 192; oB = 0; Ocnt = 1; Otot = 1;
        mw = mw3; rw = rw3; ew = ew3;
    }

    // Rinv staging with float4 loads (3969 = 992*4 + 1).
    {
        const float4* R4 = (const float4*)Rinv;
        float4* S4 = (float4*)sR;
        #pragma unroll 4
        for (int i = t; i < 992; i += 256) S4[i] = R4[i];
        if (t == 0) sR[3968] = Rinv[3968];
    }
    if (t < MM) { float u = U[t]; sEU[t] = __expf(u); sEMU[t] = __expf(-u); }
    if (t < 64) { float v = (float)t * 0.015625f; sEJ[t] = __expf(v); sEMJ[t] = __expf(-v); }
    // Zero sP/sQ so inactive segments (stage 3) scan clean values.
    sP[t] = 0.f; sQ[t] = 0.f;

    // Phase A: effective weights + weight-KL partial.
    float kl = 0.f;
    for (int i = t; i < Ocnt * MM; i += 256) {
        int ol = i / MM, n = i % MM;
        int gi = (f * Otot + oB + ol) * MM + n;
        float mu = mw[gi];
        float s  = log1pf(__expf(rw[gi]));
        sW[i] = mu + s * ew[gi];
        kl += kl_term(mu, s);
    }
    red[t] = kl;
    __syncthreads();

    // Phase B: one V entry per thread (63-FMA chain).
    for (int i = t; i < Ocnt * MM; i += 256) {
        int ol = i / MM, m = i % MM;
        const float* r = &sR[m * MM];
        const float* w = &sW[ol * MM];
        float v = 0.f;
        #pragma unroll
        for (int n = 0; n < MM; n++) v = fmaf(r[n], w[n], v);
        sP[ol * 64 + (m + 1)] = v * sEU[m];
        sQ[ol * 64 + (m + 1)] = v * sEMU[m];
    }
    __syncthreads();

    // Phase C: segmented scan over i (segments of 64 = 2 warps each).
    // A[j] = inclusive-prefix P at j; B[j] = Qtot - inclusive-prefix Q at j.
    {
        const int lane = t & 31, wid = t >> 5;
        float p = sP[t], q = sQ[t];
        #pragma unroll
        for (int d = 1; d < 32; d <<= 1) {
            float np = __shfl_up_sync(0xFFFFFFFFu, p, d);
            float nq = __shfl_up_sync(0xFFFFFFFFu, q, d);
            if (lane >= d) { p += np; q += nq; }
        }
        if (lane == 31) { wtP[wid] = p; wtQ[wid] = q; }
        __syncthreads();
        if (wid & 1) { p += wtP[wid - 1]; q += wtQ[wid - 1]; }
        int seg = t >> 6;                       // = ol
        float qtot = wtQ[seg * 2] + wtQ[seg * 2 + 1];
        float A = p;
        float B = qtot - q;

        if (t < Ocnt * 64) {
            int ol = seg, j = t & 63;
            if (stage == 1) {
                float At = A * sEMJ[j];
                float Bt = B * sEJ[j];
                g_T1[(f * 64 + j) * 16 + (oB + ol)] = make_float2(At + Bt, Bt - At);
            } else if (stage == 2) {
                g_T2[(f * 64 + j) * 16 + (oB + ol)] = make_float2(A, B);
            } else {
                g_T3[j * 16 + f] = make_float2(A, B);
            }
        }
    }

    // KL partial reduction.
    __syncthreads();
    for (int s = 128; s > 0; s >>= 1) {
        if (t < s) red[t] += red[t + s];
        __syncthreads();
    }
    if (t == 0) g_klpart[blk] = red[0];
    cudaTriggerProgrammaticLaunchCompletion();
}

// ---------------------------------------------------------------------------
// Forward. Prologue (x load + stage-1 precompute) runs BEFORE the PDL
// dependency sync; all table/bsum/klpart reads come after.
// ---------------------------------------------------------------------------
__global__ void __launch_bounds__(256) fwd_kernel(
    const float* __restrict__ x, float* __restrict__ out, int nB, int klIdx)
{
    __shared__ float2 sT[8][64];   // [warp][sub*32 + f]

    const int warp = threadIdx.x >> 5, lane = threadIdx.x & 31;
    const int sub = lane >> 4, o = lane & 15;
    const int b = blockIdx.x * 16 + warp * 2 + sub;
    const int bc = (b < nB) ? b : (nB - 1);
    const unsigned mask = 0xFFFFu << (sub << 4);

    float2* tw = &sT[warp][sub * 32];

    // ---- pre-sync: x loads + stage-1 precompute (independent of build) ----
    const float xv0 = __ldg(&x[bc * 32 + o]);
    const float xv1 = __ldg(&x[bc * 32 + 16 + o]);
    {
        float j0f = fminf(fmaxf(xv0 * 64.f, 0.f), 63.f);
        int   j0  = (int)j0f;
        float t0  = fmaf((float)j0, -0.015625f, xv0);
        float t02 = t0 * t0;
        tw[o] = make_float2(embed_j(fmaf(t02, 0.5f, 1.f), j0),
                            t0 * fmaf(t02, 0.16666667f, 1.f));
        float j1f = fminf(fmaxf(xv1 * 64.f, 0.f), 63.f);
        int   j1  = (int)j1f;
        float t1  = fmaf((float)j1, -0.015625f, xv1);
        float t12 = t1 * t1;
        tw[16 + o] = make_float2(embed_j(fmaf(t12, 0.5f, 1.f), j1),
                                 t1 * fmaf(t12, 0.16666667f, 1.f));
    }
    __syncwarp();

    // ---- wait for build_tables results to be visible ----
    cudaGridDependencySynchronize();

    // KL: warp-parallel deterministic sum of the NBLK partials.
    if (blockIdx.x == 0 && threadIdx.x < 32) {
        int l = threadIdx.x;
        float s = 0.f;
        for (int i = l; i < NBLK; i += 32) s += g_klpart[i];
        #pragma unroll
        for (int d = 16; d > 0; d >>= 1)
            s += __shfl_xor_sync(0xFFFFFFFFu, s, d);
        if (l == 0) out[klIdx] = s;
    }

    const float bs1 = __ldg(&g_bsum1[o]);
    const float bs2 = __ldg(&g_bsum2[o]);
    const float bs3 = __ldg(&g_bsum3);

    // ---- stage 1 gathers: dual accumulators (even/odd f) ----
    const char* base1 = (const char*)g_T1 + o * 8;
    float acc0 = 0.f, acc1 = 0.f;
    #pragma unroll
    for (int f = 0; f < 32; f += 2) {
        float2 tra = tw[f];
        float2 trb = tw[f + 1];
        unsigned ja = (__float_as_uint(tra.x) & 63u) << 7;   // j*128
        unsigned jb = (__float_as_uint(trb.x) & 63u) << 7;
        const float2 pqa = *(const float2*)(base1 + f * 8192 + ja);
        const float2 pqb = *(const float2*)(base1 + (f + 1) * 8192 + jb);
        acc0 = fmaf(pqa.x, tra.x, fmaf(pqa.y, tra.y, acc0));
        acc1 = fmaf(pqb.x, trb.x, fmaf(pqb.y, trb.y, acc1));
    }
    float h1 = (acc0 + acc1) + bs1;
    __syncwarp();

    // ---- stage 2 precompute: (e^{-h} [low bits = j], e^{h}) ----
    {
        float ex  = __expf(h1);
        float emx = __expf(-h1);
        int j = (int)fminf(fmaxf(h1 * 64.f, 0.f), 63.f);
        tw[o] = make_float2(embed_j(emx, j), ex);
    }
    __syncwarp();

    // ---- stage 2 gathers: dual accumulators ----
    const char* base2 = (const char*)g_T2 + o * 8;
    acc0 = 0.f; acc1 = 0.f;
    #pragma unroll
    for (int f = 0; f < 16; f += 2) {
        float2 tra = tw[f];
        float2 trb = tw[f + 1];
        unsigned ja = (__float_as_uint(tra.x) & 63u) << 7;
        unsigned jb = (__float_as_uint(trb.x) & 63u) << 7;
        const float2 aba = *(const float2*)(base2 + f * 8192 + ja);
        const float2 abb = *(const float2*)(base2 + (f + 1) * 8192 + jb);
        acc0 = fmaf(tra.x, aba.x, fmaf(tra.y, aba.y, acc0));
        acc1 = fmaf(trb.x, abb.x, fmaf(trb.y, abb.y, acc1));
    }
    float h2 = (acc0 + acc1) + bs2;

    // ---- stage 3: 16 -> 1 (lane o is feature o) ----
    {
        float ex  = __expf(h2);
        float emx = __expf(-h2);
        int j = (int)fminf(fmaxf(h2 * 64.f, 0.f), 63.f);
        float2 tv = __ldg(&g_T3[j * 16 + o]);
        float c = fmaf(emx, tv.x, ex * tv.y);
        c += __shfl_xor_sync(mask, c, 8);
        c += __shfl_xor_sync(mask, c, 4);
        c += __shfl_xor_sync(mask, c, 2);
        c += __shfl_xor_sync(mask, c, 1);
        if (o == 0 && b < nB) out[b] = c + bs3;
    }
}

// ---------------------------------------------------------------------------
extern "C" void kernel_launch(void* const* d_in, const int* in_sizes, int n_in,
                              void* d_out, int out_size)
{
    const float* x    = (const float*)d_in[0];
    const float* U    = (const float*)d_in[1];
    const float* Rinv = (const float*)d_in[2];

    const float* mw1 = (const float*)d_in[3];
    const float* rw1 = (const float*)d_in[4];
    const float* mb1 = (const float*)d_in[5];
    const float* rb1 = (const float*)d_in[6];
    const float* ew1 = (const float*)d_in[7];
    const float* eb1 = (const float*)d_in[8];

    const float* mw2 = (const float*)d_in[9];
    const float* rw2 = (const float*)d_in[10];
    const float* mb2 = (const float*)d_in[11];
    const float* rb2 = (const float*)d_in[12];
    const float* ew2 = (const float*)d_in[13];
    const float* eb2 = (const float*)d_in[14];

    const float* mw3 = (const float*)d_in[15];
    const float* rw3 = (const float*)d_in[16];
    const float* mb3 = (const float*)d_in[17];
    const float* rb3 = (const float*)d_in[18];
    const float* ew3 = (const float*)d_in[19];
    const float* eb3 = (const float*)d_in[20];

    const int nB = in_sizes[0] / 32;
    float* out = (float*)d_out;

    build_tables<<<NBLK, 256>>>(U, Rinv,
                                mw1, rw1, ew1, mw2, rw2, ew2, mw3, rw3, ew3,
                                mb1, rb1, eb1, mb2, rb2, eb2, mb3, rb3, eb3);

    // fwd with programmatic dependent launch: starts while build drains;
    // pre-sync section only touches x.
    cudaLaunchConfig_t cfg = {};
    cfg.gridDim  = dim3((unsigned)((nB + 15) / 16));
    cfg.blockDim = dim3(256);
    cudaLaunchAttribute attrs[1];
    attrs[0].id = cudaLaunchAttributeProgrammaticStreamSerialization;
    attrs[0].val.programmaticStreamSerializationAllowed = 1;
    cfg.attrs = attrs;
    cfg.numAttrs = 1;
    cudaLaunchKernelEx(&cfg, fwd_kernel, x, out, nB, out_size - 1);
}

// round 17
// speedup vs baseline: 1.5409x; 1.0035x over previous
#include <cuda_runtime.h>
#include <cuda_bf16.h>

// AdditiveDTMGP: 3-stage additive deep GP, Laplace kernel on dyadic design
// u_i = i/64 (i=1..63), whitened by Rinv (upper-triangular), reparam weights.
//
// Exact split: exp(-|x-u|) = e^{-x}e^{u} (u<=x) / e^{x}e^{-u} (u>x) collapses
// each 63-term sum to a 2-term table lookup at j = floor(64x). Stage 1 tables
// premultiplied by e^{-+j/64}, stored (P,Q) fp32. Stages 2/3 exact (A,B)+exp.
//
// R12 architecture (separate build + fwd under PDL; fusion R13-R15 dead).
// R17: build restructured to a SINGLE WAVE — 113 blocks (<=148 SMs):
//   stage1 64 blocks (Ocnt=8), stage2 32 blocks (Ocnt=8), stage3 16, bias 1.
// Per-thread Phase B becomes 2 independent 63-FMA chains (ILP), Phase C a
// two-round segmented scan. KL reduction before the PDL trigger.

#define MM 63
#define NBLK 113   // 64 stage1 + 32 stage2 + 16 stage3 + 1 bias

__device__ float2 g_T1[32 * 64 * 16];   // stage1 [f][j][o] : (P, Q)
__device__ float2 g_T2[16 * 64 * 16];   // stage2 [f][j][o] : (A, B)
__device__ float2 g_T3[64 * 16];        // stage3 [j][f]    : (A, B)
__device__ float  g_bsum1[16];
__device__ float  g_bsum2[16];
__device__ float  g_bsum3;
__device__ float  g_klpart[NBLK];

__device__ __forceinline__ float kl_term(float mu, float s) {
    return fmaf(0.5f, fmaf(s, s, mu * mu), -__logf(s)) - 0.5f;
}

// Embed 6-bit j into low mantissa bits of v (rounded): <= ~63-ulp perturbation.
__device__ __forceinline__ float embed_j(float v, int j) {
    unsigned b = (__float_as_uint(v) + 32u) & ~63u;
    return __uint_as_float(b | (unsigned)j);
}

// ---------------------------------------------------------------------------
// Prep: 113 blocks, single wave.
//   [0,64)   stage1: f = blk>>1, o-range [(blk&1)*8, +8)
//   [64,96)  stage2: f = (blk-64)>>1, o-range [(blk&1)*8, +8)
//   [96,112) stage3: f = blk-96, O=1
//   112      bias sums + bias-KL
// ---------------------------------------------------------------------------
__global__ void __launch_bounds__(256) build_tables(
    const float* __restrict__ U, const float* __restrict__ Rinv,
    const float* __restrict__ mw1, const float* __restrict__ rw1, const float* __restrict__ ew1,
    const float* __restrict__ mw2, const float* __restrict__ rw2, const float* __restrict__ ew2,
    const float* __restrict__ mw3, const float* __restrict__ rw3, const float* __restrict__ ew3,
    const float* __restrict__ mb1, const float* __restrict__ rb1, const float* __restrict__ eb1,
    const float* __restrict__ mb2, const float* __restrict__ rb2, const float* __restrict__ eb2,
    const float* __restrict__ mb3, const float* __restrict__ rb3, const float* __restrict__ eb3)
{
    const int blk = blockIdx.x, t = threadIdx.x;
    __shared__ float red[256];

    if (blk == 112) {
        float kl = 0.f;
        for (int i = t; i < 32 * 16; i += 256) kl += kl_term(mb1[i], log1pf(__expf(rb1[i])));
        for (int i = t; i < 16 * 16; i += 256) kl += kl_term(mb2[i], log1pf(__expf(rb2[i])));
        for (int i = t; i < 16;      i += 256) kl += kl_term(mb3[i], log1pf(__expf(rb3[i])));
        if (t < 16) {
            float s = 0.f;
            for (int f = 0; f < 32; f++) {
                int i = f * 16 + t;
                s += mb1[i] + log1pf(__expf(rb1[i])) * eb1[i];
            }
            g_bsum1[t] = s;
        } else if (t < 32) {
            int o = t - 16;
            float s = 0.f;
            for (int f = 0; f < 16; f++) {
                int i = f * 16 + o;
                s += mb2[i] + log1pf(__expf(rb2[i])) * eb2[i];
            }
            g_bsum2[o] = s;
        } else if (t == 32) {
            float s = 0.f;
            for (int f = 0; f < 16; f++)
                s += mb3[f] + log1pf(__expf(rb3[f])) * eb3[f];
            g_bsum3 = s;
        }
        red[t] = kl;
        __syncthreads();
        for (int s = 128; s > 0; s >>= 1) {
            if (t < s) red[t] += red[t + s];
            __syncthreads();
        }
        if (t == 0) g_klpart[112] = red[0];
        cudaTriggerProgrammaticLaunchCompletion();
        return;
    }

    __shared__ float sR[MM * MM + 1];
    __shared__ float sW[8 * MM];
    __shared__ float sP[8 * 64];   // P[ol][i] = e^{i/64} V[ol][i-1], i=1..63
    __shared__ float sQ[8 * 64];
    __shared__ float sEU[MM], sEMU[MM];
    __shared__ float sEJ[64], sEMJ[64];
    __shared__ float wtP[8], wtQ[8];

    int stage, f, oB, Ocnt, Otot;
    const float *mw, *rw, *ew;
    if (blk < 64) {
        stage = 1; f = blk >> 1; oB = (blk & 1) * 8; Ocnt = 8; Otot = 16;
        mw = mw1; rw = rw1; ew = ew1;
    } else if (blk < 96) {
        int bb = blk - 64;
        stage = 2; f = bb >> 1; oB = (bb & 1) * 8; Ocnt = 8; Otot = 16;
        mw = mw2; rw = rw2; ew = ew2;
    } else {
        stage = 3; f = blk - 96; oB = 0; Ocnt = 1; Otot = 1;
        mw = mw3; rw = rw3; ew = ew3;
    }

    // Rinv staging with float4 loads (3969 = 992*4 + 1).
    {
        const float4* R4 = (const float4*)Rinv;
        float4* S4 = (float4*)sR;
        #pragma unroll 4
        for (int i = t; i < 992; i += 256) S4[i] = R4[i];
        if (t == 0) sR[3968] = Rinv[3968];
    }
    if (t < MM) { float u = U[t]; sEU[t] = __expf(u); sEMU[t] = __expf(-u); }
    if (t < 64) { float v = (float)t * 0.015625f; sEJ[t] = __expf(v); sEMJ[t] = __expf(-v); }
    // Zero sP/sQ (512 entries) so inactive segments scan clean values.
    sP[t] = 0.f; sQ[t] = 0.f;
    sP[t + 256] = 0.f; sQ[t + 256] = 0.f;

    // Phase A: effective weights + weight-KL partial.
    float kl = 0.f;
    for (int i = t; i < Ocnt * MM; i += 256) {
        int ol = i / MM, n = i % MM;
        int gi = (f * Otot + oB + ol) * MM + n;
        float mu = mw[gi];
        float s  = log1pf(__expf(rw[gi]));
        sW[i] = mu + s * ew[gi];
        kl += kl_term(mu, s);
    }
    red[t] = kl;
    __syncthreads();

    // Phase B: V entries, up to 2 independent 63-FMA chains per thread (ILP).
    for (int i = t; i < Ocnt * MM; i += 256) {
        int ol = i / MM, m = i % MM;
        const float* r = &sR[m * MM];
        const float* w = &sW[ol * MM];
        float v = 0.f;
        #pragma unroll
        for (int n = 0; n < MM; n++) v = fmaf(r[n], w[n], v);
        sP[ol * 64 + (m + 1)] = v * sEU[m];
        sQ[ol * 64 + (m + 1)] = v * sEMU[m];
    }
    __syncthreads();

    // KL partial reduction (before Phase C so everything precedes trigger).
    for (int s = 128; s > 0; s >>= 1) {
        if (t < s) red[t] += red[t + s];
        __syncthreads();
    }
    if (t == 0) g_klpart[blk] = red[0];

    // Phase C: two-round segmented scan (4 segments of 64 per round).
    // A[j] = inclusive-prefix P at j; B[j] = Qtot - inclusive-prefix Q at j.
    const int lane = t & 31, wid = t >> 5;
    #pragma unroll
    for (int rd = 0; rd < 2; rd++) {
        int e = (rd << 8) + t;
        float p = sP[e], q = sQ[e];
        #pragma unroll
        for (int d = 1; d < 32; d <<= 1) {
            float np = __shfl_up_sync(0xFFFFFFFFu, p, d);
            float nq = __shfl_up_sync(0xFFFFFFFFu, q, d);
            if (lane >= d) { p += np; q += nq; }
        }
        if (lane == 31) { wtP[wid] = p; wtQ[wid] = q; }
        __syncthreads();
        if (wid & 1) { p += wtP[wid - 1]; q += wtQ[wid - 1]; }
        int segL = t >> 6;                       // segment within round
        float qtot = wtQ[segL * 2] + wtQ[segL * 2 + 1];
        float A = p;
        float B = qtot - q;

        if (e < Ocnt * 64) {
            int ol = e >> 6, j = e & 63;
            if (stage == 1) {
                float At = A * sEMJ[j];
                float Bt = B * sEJ[j];
                g_T1[(f * 64 + j) * 16 + (oB + ol)] = make_float2(At + Bt, Bt - At);
            } else if (stage == 2) {
                g_T2[(f * 64 + j) * 16 + (oB + ol)] = make_float2(A, B);
            } else {
                g_T3[j * 16 + f] = make_float2(A, B);
            }
        }
        __syncthreads();   // wtP/wtQ reuse safety between rounds
    }
    cudaTriggerProgrammaticLaunchCompletion();
}

// ---------------------------------------------------------------------------
// Forward. Prologue (x load + stage-1 precompute) runs BEFORE the PDL
// dependency sync; all table/bsum/klpart reads come after.
// ---------------------------------------------------------------------------
__global__ void __launch_bounds__(256) fwd_kernel(
    const float* __restrict__ x, float* __restrict__ out, int nB, int klIdx)
{
    __shared__ float2 sT[8][64];   // [warp][sub*32 + f]

    const int warp = threadIdx.x >> 5, lane = threadIdx.x & 31;
    const int sub = lane >> 4, o = lane & 15;
    const int b = blockIdx.x * 16 + warp * 2 + sub;
    const int bc = (b < nB) ? b : (nB - 1);
    const unsigned mask = 0xFFFFu << (sub << 4);

    float2* tw = &sT[warp][sub * 32];

    // ---- pre-sync: x loads + stage-1 precompute (independent of build) ----
    const float xv0 = __ldg(&x[bc * 32 + o]);
    const float xv1 = __ldg(&x[bc * 32 + 16 + o]);
    {
        float j0f = fminf(fmaxf(xv0 * 64.f, 0.f), 63.f);
        int   j0  = (int)j0f;
        float t0  = fmaf((float)j0, -0.015625f, xv0);
        float t02 = t0 * t0;
        tw[o] = make_float2(embed_j(fmaf(t02, 0.5f, 1.f), j0),
                            t0 * fmaf(t02, 0.16666667f, 1.f));
        float j1f = fminf(fmaxf(xv1 * 64.f, 0.f), 63.f);
        int   j1  = (int)j1f;
        float t1  = fmaf((float)j1, -0.015625f, xv1);
        float t12 = t1 * t1;
        tw[16 + o] = make_float2(embed_j(fmaf(t12, 0.5f, 1.f), j1),
                                 t1 * fmaf(t12, 0.16666667f, 1.f));
    }
    __syncwarp();

    // ---- wait for build_tables results to be visible ----
    cudaGridDependencySynchronize();

    // KL: warp-parallel deterministic sum of the NBLK partials.
    if (blockIdx.x == 0 && threadIdx.x < 32) {
        int l = threadIdx.x;
        float s = 0.f;
        for (int i = l; i < NBLK; i += 32) s += g_klpart[i];
        #pragma unroll
        for (int d = 16; d > 0; d >>= 1)
            s += __shfl_xor_sync(0xFFFFFFFFu, s, d);
        if (l == 0) out[klIdx] = s;
    }

    const float bs1 = __ldg(&g_bsum1[o]);
    const float bs2 = __ldg(&g_bsum2[o]);
    const float bs3 = __ldg(&g_bsum3);

    // ---- stage 1 gathers: dual accumulators (even/odd f) ----
    const char* base1 = (const char*)g_T1 + o * 8;
    float acc0 = 0.f, acc1 = 0.f;
    #pragma unroll
    for (int f = 0; f < 32; f += 2) {
        float2 tra = tw[f];
        float2 trb = tw[f + 1];
        unsigned ja = (__float_as_uint(tra.x) & 63u) << 7;   // j*128
        unsigned jb = (__float_as_uint(trb.x) & 63u) << 7;
        const float2 pqa = *(const float2*)(base1 + f * 8192 + ja);
        const float2 pqb = *(const float2*)(base1 + (f + 1) * 8192 + jb);
        acc0 = fmaf(pqa.x, tra.x, fmaf(pqa.y, tra.y, acc0));
        acc1 = fmaf(pqb.x, trb.x, fmaf(pqb.y, trb.y, acc1));
    }
    float h1 = (acc0 + acc1) + bs1;
    __syncwarp();

    // ---- stage 2 precompute: (e^{-h} [low bits = j], e^{h}) ----
    {
        float ex  = __expf(h1);
        float emx = __expf(-h1);
        int j = (int)fminf(fmaxf(h1 * 64.f, 0.f), 63.f);
        tw[o] = make_float2(embed_j(emx, j), ex);
    }
    __syncwarp();

    // ---- stage 2 gathers: dual accumulators ----
    const char* base2 = (const char*)g_T2 + o * 8;
    acc0 = 0.f; acc1 = 0.f;
    #pragma unroll
    for (int f = 0; f < 16; f += 2) {
        float2 tra = tw[f];
        float2 trb = tw[f + 1];
        unsigned ja = (__float_as_uint(tra.x) & 63u) << 7;
        unsigned jb = (__float_as_uint(trb.x) & 63u) << 7;
        const float2 aba = *(const float2*)(base2 + f * 8192 + ja);
        const float2 abb = *(const float2*)(base2 + (f + 1) * 8192 + jb);
        acc0 = fmaf(tra.x, aba.x, fmaf(tra.y, aba.y, acc0));
        acc1 = fmaf(trb.x, abb.x, fmaf(trb.y, abb.y, acc1));
    }
    float h2 = (acc0 + acc1) + bs2;

    // ---- stage 3: 16 -> 1 (lane o is feature o) ----
    {
        float ex  = __expf(h2);
        float emx = __expf(-h2);
        int j = (int)fminf(fmaxf(h2 * 64.f, 0.f), 63.f);
        float2 tv = __ldg(&g_T3[j * 16 + o]);
        float c = fmaf(emx, tv.x, ex * tv.y);
        c += __shfl_xor_sync(mask, c, 8);
        c += __shfl_xor_sync(mask, c, 4);
        c += __shfl_xor_sync(mask, c, 2);
        c += __shfl_xor_sync(mask, c, 1);
        if (o == 0 && b < nB) out[b] = c + bs3;
    }
}

// ---------------------------------------------------------------------------
extern "C" void kernel_launch(void* const* d_in, const int* in_sizes, int n_in,
                              void* d_out, int out_size)
{
    const float* x    = (const float*)d_in[0];
    const float* U    = (const float*)d_in[1];
    const float* Rinv = (const float*)d_in[2];

    const float* mw1 = (const float*)d_in[3];
    const float* rw1 = (const float*)d_in[4];
    const float* mb1 = (const float*)d_in[5];
    const float* rb1 = (const float*)d_in[6];
    const float* ew1 = (const float*)d_in[7];
    const float* eb1 = (const float*)d_in[8];

    const float* mw2 = (const float*)d_in[9];
    const float* rw2 = (const float*)d_in[10];
    const float* mb2 = (const float*)d_in[11];
    const float* rb2 = (const float*)d_in[12];
    const float* ew2 = (const float*)d_in[13];
    const float* eb2 = (const float*)d_in[14];

    const float* mw3 = (const float*)d_in[15];
    const float* rw3 = (const float*)d_in[16];
    const float* mb3 = (const float*)d_in[17];
    const float* rb3 = (const float*)d_in[18];
    const float* ew3 = (const float*)d_in[19];
    const float* eb3 = (const float*)d_in[20];

    const int nB = in_sizes[0] / 32;
    float* out = (float*)d_out;

    build_tables<<<NBLK, 256>>>(U, Rinv,
                                mw1, rw1, ew1, mw2, rw2, ew2, mw3, rw3, ew3,
                                mb1, rb1, eb1, mb2, rb2, eb2, mb3, rb3, eb3);

    // fwd with programmatic dependent launch: starts while build drains;
    // pre-sync section only touches x.
    cudaLaunchConfig_t cfg = {};
    cfg.gridDim  = dim3((unsigned)((nB + 15) / 16));
    cfg.blockDim = dim3(256);
    cudaLaunchAttribute attrs[1];
    attrs[0].id = cudaLaunchAttributeProgrammaticStreamSerialization;
    attrs[0].val.programmaticStreamSerializationAllowed = 1;
    cfg.attrs = attrs;
    cfg.numAttrs = 1;
    cudaLaunchKernelEx(&cfg, fwd_kernel, x, out, nB, out_size - 1);
}